// round 4
// baseline (speedup 1.0000x reference)
#include <cuda_runtime.h>
#include <cuda_bf16.h>
#include <cstdint>

#define SEQ   65536
#define HID   1024
#define EMB   512
#define NCH   512
#define SCTA  64         // scan CTAs
#define SROW  16         // rows per scan CTA (one per warp)

// ---------------- device scratch (static allocation only) ----------------
struct __align__(8) Pub { unsigned int v; unsigned int tag; };
__device__ Pub   g_h[2][HID];                    // ping-pong (value,tag) pairs
__device__ float g_xp[(size_t)SEQ * HID];        // x projections  (256 MB)
__device__ float g_hs[(size_t)SEQ * HID];        // hidden states  (256 MB)

// ---------------- small helpers ----------------
__device__ __forceinline__ void st_pair(Pub* p, float val, unsigned tag) {
    unsigned long long u = ((unsigned long long)tag << 32) |
                           (unsigned long long)__float_as_uint(val);
    asm volatile("st.global.relaxed.gpu.b64 [%0], %1;" :: "l"(p), "l"(u) : "memory");
}
__device__ __forceinline__ unsigned long long ld_pair(const Pub* p) {
    unsigned long long u;
    asm volatile("ld.global.relaxed.gpu.b64 %0, [%1];" : "=l"(u) : "l"(p) : "memory");
    return u;
}
// wait until tag == s; fast raw spin first, then nanosleep backoff
__device__ __forceinline__ float wait_pair(const Pub* p, unsigned s) {
    unsigned long long u = ld_pair(p);
    int spins = 0;
    while ((unsigned)(u >> 32) != s) {
        if (++spins > 32) __nanosleep(20);
        u = ld_pair(p);
    }
    return __uint_as_float((unsigned)u);
}

// ---------------- init: clear tags each launch (graph replays!) ----------------
__global__ void init_tags_kernel() {
    unsigned long long* p = (unsigned long long*)g_h;
    for (int i = threadIdx.x; i < 2 * HID; i += blockDim.x) p[i] = 0ULL;
}

// ---------------- fp32 SGEMM:  C[M,N] = A[M,K] * B[N,K]^T (+bias) ----------------
template<bool GATHER, bool BIAS>
__global__ void __launch_bounds__(256) sgemm_tn(
    const float* __restrict__ A, const float* __restrict__ B,
    float* __restrict__ C, const int* __restrict__ idx,
    const float* __restrict__ bias, int M, int N, int K)
{
    __shared__ __align__(16) float As[8][132];
    __shared__ __align__(16) float Bs[8][132];
    __shared__ int sidx[128];

    const int tid = threadIdx.x;
    const int bm  = blockIdx.y * 128;
    const int bn  = blockIdx.x * 128;

    if (GATHER && tid < 128) sidx[tid] = idx[bm + tid];
    __syncthreads();

    const int tx = tid & 15;          // 0..15 -> n
    const int ty = tid >> 4;          // 0..15 -> m
    const int arow = tid >> 1;        // 0..127
    const int akq  = (tid & 1) * 4;   // 0 or 4

    const float* Arow = GATHER ? (A + (size_t)sidx[arow] * K)
                               : (A + (size_t)(bm + arow) * K);
    const float* Brow = B + (size_t)(bn + arow) * K;

    float acc[8][8];
    #pragma unroll
    for (int i = 0; i < 8; i++)
        #pragma unroll
        for (int j = 0; j < 8; j++) acc[i][j] = 0.f;

    for (int kt = 0; kt < K; kt += 8) {
        float4 av = *(const float4*)(Arow + kt + akq);
        float4 bv = *(const float4*)(Brow + kt + akq);
        __syncthreads();
        As[akq+0][arow] = av.x; As[akq+1][arow] = av.y;
        As[akq+2][arow] = av.z; As[akq+3][arow] = av.w;
        Bs[akq+0][arow] = bv.x; Bs[akq+1][arow] = bv.y;
        Bs[akq+2][arow] = bv.z; Bs[akq+3][arow] = bv.w;
        __syncthreads();
        #pragma unroll
        for (int k = 0; k < 8; k++) {
            float ra[8], rb[8];
            #pragma unroll
            for (int i = 0; i < 8; i++) ra[i] = As[k][ty * 8 + i];
            #pragma unroll
            for (int j = 0; j < 8; j++) rb[j] = Bs[k][tx * 8 + j];
            #pragma unroll
            for (int i = 0; i < 8; i++)
                #pragma unroll
                for (int j = 0; j < 8; j++) acc[i][j] += ra[i] * rb[j];
        }
    }

    float bload[8];
    #pragma unroll
    for (int j = 0; j < 8; j++) bload[j] = BIAS ? bias[bn + tx * 8 + j] : 0.f;

    #pragma unroll
    for (int i = 0; i < 8; i++) {
        size_t row = (size_t)(bm + ty * 8 + i);
        float* cp = C + row * N + bn + tx * 8;
        float4 v0, v1;
        v0.x = acc[i][0] + bload[0]; v0.y = acc[i][1] + bload[1];
        v0.z = acc[i][2] + bload[2]; v0.w = acc[i][3] + bload[3];
        v1.x = acc[i][4] + bload[4]; v1.y = acc[i][5] + bload[5];
        v1.z = acc[i][6] + bload[6]; v1.w = acc[i][7] + bload[7];
        *(float4*)(cp)     = v0;
        *(float4*)(cp + 4) = v1;
    }
}

// ---------------- the scan ----------------
// 64 CTAs x 512 threads. One warp owns one row of Waa (16 rows/CTA):
//   lane l holds weights for columns {l, l+32, ..., l+992} in registers.
// Per step: each thread polls 2 (val,tag) pairs into double-buffered sh,
// ONE __syncthreads, then each warp dot-products its row, butterfly-reduces,
// and lane 0 publishes tanh(xp + dot) immediately (rows fully decoupled).
// WAR safety of sh[slot]: overwriting slot s&1 (during staging of step s+2)
// requires the writer to have passed bar(s+1) in its own CTA, which (program
// order) requires every warp of that CTA to have finished its step-s reads.
__global__ void __launch_bounds__(512, 1) scan_kernel(const float* __restrict__ Waa)
{
    __shared__ __align__(16) float sh[2][HID];   // double-buffered staged h

    const int tid = threadIdx.x;
    const int w = tid >> 5, l = tid & 31;
    const int row = blockIdx.x * SROW + w;

    // weights: 32 per lane, strided by 32 (coalesced loads, conflict-free LDS)
    float wr[32];
    {
        const float* wbase = Waa + (size_t)row * HID + l;
        #pragma unroll
        for (int k = 0; k < 32; k++) wr[k] = __ldg(&wbase[32 * k]);
    }

    // step 0: h_1 = tanh(xp[0]) (h_0 == 0 -> no matvec, no wait)
    if (l == 0) {
        float v = tanhf(g_xp[row]);
        st_pair(&g_h[1][row], v, 1u);
        g_hs[row] = v;
    }

    for (int s = 1; s < SEQ; s++) {
        const int slot = s & 1;
        // prefetch xp (independent of h -> overlaps polling)
        float xpv = 0.f;
        if (l == 0) xpv = __ldcg(&g_xp[(size_t)s * HID + row]);

        // stage h_s: two pairs per thread
        sh[slot][tid]       = wait_pair(&g_h[slot][tid],       (unsigned)s);
        sh[slot][tid + 512] = wait_pair(&g_h[slot][tid + 512], (unsigned)s);
        __syncthreads();   // the ONLY barrier per step

        // row dot product: 32 strided LDS + FMA, 4 accumulators
        const float* hrow = &sh[slot][l];
        float a0 = 0.f, a1 = 0.f, a2 = 0.f, a3 = 0.f;
        #pragma unroll
        for (int k = 0; k < 32; k += 4) {
            a0 += wr[k+0] * hrow[32*(k+0)];
            a1 += wr[k+1] * hrow[32*(k+1)];
            a2 += wr[k+2] * hrow[32*(k+2)];
            a3 += wr[k+3] * hrow[32*(k+3)];
        }
        float a = (a0 + a1) + (a2 + a3);
        #pragma unroll
        for (int off = 16; off > 0; off >>= 1)
            a += __shfl_xor_sync(0xffffffffu, a, off);

        // lane 0: finalize + publish immediately (no second barrier)
        if (l == 0) {
            const float v = tanhf(xpv + a);
            st_pair(&g_h[(s + 1) & 1][row], v, (unsigned)(s + 1));  // critical path first
            g_hs[(size_t)s * HID + row] = v;
        }
    }
}

// ---------------- h_last epilogue ----------------
__global__ void copy_hlast_kernel(float* __restrict__ out) {
    const int i = threadIdx.x;                 // 1024 threads
    out[(size_t)SEQ * NCH + i] = __uint_as_float(g_h[0][i].v);  // S even -> slot 0
}

// ---------------- launch ----------------
extern "C" void kernel_launch(void* const* d_in, const int* in_sizes, int n_in,
                              void* d_out, int out_size)
{
    const int*   input_seq = (const int*)  d_in[0];
    const float* emb       = (const float*)d_in[1];
    const float* Wax       = (const float*)d_in[2];
    const float* Waa       = (const float*)d_in[3];
    const float* Wya       = (const float*)d_in[4];
    const float* b_y       = (const float*)d_in[5];
    float* out = (float*)d_out;

    float* xp_ptr = nullptr;
    float* hs_ptr = nullptr;
    cudaGetSymbolAddress((void**)&xp_ptr, g_xp);
    cudaGetSymbolAddress((void**)&hs_ptr, g_hs);

    // 1) x_proj[s,h] = sum_e emb_table[input_seq[s],e] * Wax[h,e]
    {
        dim3 grid(HID / 128, SEQ / 128);
        sgemm_tn<true, false><<<grid, 256>>>(emb, Wax, xp_ptr, input_seq, nullptr,
                                             SEQ, HID, EMB);
    }
    // 2) reset publish tags, then the sequential scan
    init_tags_kernel<<<1, 256>>>();
    scan_kernel<<<SCTA, 512>>>(Waa);
    // 3) out[s,v] = sum_h hs[s,h] * Wya[v,h] + b_y[v]
    {
        dim3 grid(NCH / 128, SEQ / 128);
        sgemm_tn<false, true><<<grid, 256>>>(hs_ptr, Wya, out, nullptr, b_y,
                                             SEQ, NCH, HID);
    }
    // 4) append h_last
    copy_hlast_kernel<<<1, HID>>>(out);
}